// round 1
// baseline (speedup 1.0000x reference)
#include <cuda_runtime.h>
#include <cuda_fp16.h>
#include <cstdint>

#define T_STEPS 300
#define BATCH   256
#define NIN     128
#define NH      512
#define NOUT    3
#define DTSEC   0.01f
#define ALPHA_N 0.2f

#define Y_SIZE (BATCH * T_STEPS * NOUT)   // 230400 floats

// ---------------- device scratch (static, allocation-free) ----------------
__device__ float     g_drive[(size_t)T_STEPS * BATCH * NH];   // 157 MB
__device__ uint32_t  g_wrnnp[(NH / 2) * NH];                  // packed half2 pairs (k-pairs x h)
__device__ uint32_t  g_winp[(NIN / 2) * NH];                  // packed half2 pairs
__device__ float     g_wout[NH * NOUT];
__device__ __half    g_rpost[2 * BATCH * NH];                 // double-buffered activations (fp16)
__device__ float     g_yraw[(size_t)T_STEPS * BATCH * NOUT];
__device__ unsigned  g_bar[16 * T_STEPS];                     // per (b-group, step) barrier slots

// ---------------- prep: effective weights + packing + barrier reset --------
__global__ void prep_kernel(const float* __restrict__ w_in, const float* __restrict__ w_in_mask,
                            const float* __restrict__ w_rnn_base, const float* __restrict__ conn,
                            const float* __restrict__ ei, const float* __restrict__ w_out,
                            const float* __restrict__ w_out_mask)
{
    int tid = blockIdx.x * blockDim.x + threadIdx.x;
    int nth = gridDim.x * blockDim.x;

    // w_rnn = ei @ relu(w_rnn_base * conn): row k scaled by sign ei[k,k]
    for (int i = tid; i < (NH / 2) * NH; i += nth) {
        int p = i >> 9, h = i & (NH - 1);
        int k0 = 2 * p, k1 = 2 * p + 1;
        float s0 = ei[k0 * NH + k0];
        float s1 = ei[k1 * NH + k1];
        float v0 = fmaxf(w_rnn_base[k0 * NH + h] * conn[k0 * NH + h], 0.f) * s0;
        float v1 = fmaxf(w_rnn_base[k1 * NH + h] * conn[k1 * NH + h], 0.f) * s1;
        __half2 hv = __floats2half2_rn(v0, v1);
        g_wrnnp[i] = *reinterpret_cast<uint32_t*>(&hv);
    }
    for (int i = tid; i < (NIN / 2) * NH; i += nth) {
        int p = i >> 9, h = i & (NH - 1);
        float v0 = w_in[(2 * p) * NH + h] * w_in_mask[(2 * p) * NH + h];
        float v1 = w_in[(2 * p + 1) * NH + h] * w_in_mask[(2 * p + 1) * NH + h];
        __half2 hv = __floats2half2_rn(v0, v1);
        g_winp[i] = *reinterpret_cast<uint32_t*>(&hv);
    }
    for (int i = tid; i < NH * NOUT; i += nth)
        g_wout[i] = fmaxf(w_out[i] * w_out_mask[i], 0.f);
    for (int i = tid; i < 16 * T_STEPS; i += nth)
        g_bar[i] = 0u;
}

// ---------------- drive GEMM: drive = 0.2*(inp@w_in_eff + b_rnn) + noise ---
// M = T*B = 76800, N = 512, K = 128. fp16 mma, fp32 accum.
__global__ void __launch_bounds__(256) drive_gemm(const float* __restrict__ inp,
                                                  const float* __restrict__ noise,
                                                  const float* __restrict__ b_rnn)
{
    __shared__ __half   a_s[64 * 136];   // 64 rows x 128 k, pad 8 halves
    __shared__ uint32_t b_s[64 * 68];    // 64 k-pairs x 64 n, pad 4

    int row0 = blockIdx.x * 64;
    int n0   = blockIdx.y * 64;
    int tid  = threadIdx.x;

    #pragma unroll
    for (int j = 0; j < 32; j++) {
        int idx = tid + j * 256;
        int i = idx >> 7, k = idx & 127;
        a_s[i * 136 + k] = __float2half_rn(inp[(size_t)(row0 + i) * NIN + k]);
    }
    #pragma unroll
    for (int j = 0; j < 16; j++) {
        int idx = tid + j * 256;
        int p = idx >> 6, c = idx & 63;
        b_s[p * 68 + c] = g_winp[p * NH + n0 + c];
    }
    __syncthreads();

    int w = tid >> 5, lane = tid & 31;
    int g = lane >> 2, t = lane & 3;
    int m0 = (w & 3) * 16;
    int nw = (w >> 2) * 32;

    float acc[4][4] = {};
    #pragma unroll
    for (int kk = 0; kk < 8; kk++) {
        int k0 = kk * 16;
        uint32_t a0 = *reinterpret_cast<const uint32_t*>(&a_s[(m0 + g) * 136 + k0 + 2 * t]);
        uint32_t a1 = *reinterpret_cast<const uint32_t*>(&a_s[(m0 + g + 8) * 136 + k0 + 2 * t]);
        uint32_t a2 = *reinterpret_cast<const uint32_t*>(&a_s[(m0 + g) * 136 + k0 + 8 + 2 * t]);
        uint32_t a3 = *reinterpret_cast<const uint32_t*>(&a_s[(m0 + g + 8) * 136 + k0 + 8 + 2 * t]);
        #pragma unroll
        for (int s = 0; s < 4; s++) {
            int col = nw + 8 * s + g;
            uint32_t b0 = b_s[(kk * 8 + t) * 68 + col];
            uint32_t b1 = b_s[(kk * 8 + t + 4) * 68 + col];
            asm volatile("mma.sync.aligned.m16n8k16.row.col.f32.f16.f16.f32 "
                         "{%0,%1,%2,%3}, {%4,%5,%6,%7}, {%8,%9}, {%0,%1,%2,%3};"
                         : "+f"(acc[s][0]), "+f"(acc[s][1]), "+f"(acc[s][2]), "+f"(acc[s][3])
                         : "r"(a0), "r"(a1), "r"(a2), "r"(a3), "r"(b0), "r"(b1));
        }
    }

    #pragma unroll
    for (int s = 0; s < 4; s++) {
        int gc  = n0 + nw + 8 * s + 2 * t;
        float br0 = b_rnn[gc], br1 = b_rnn[gc + 1];
        int r0 = row0 + m0 + g;
        int r1 = r0 + 8;
        float2 nz0 = *reinterpret_cast<const float2*>(&noise[(size_t)r0 * NH + gc]);
        float2 nz1 = *reinterpret_cast<const float2*>(&noise[(size_t)r1 * NH + gc]);
        float2 d0, d1;
        d0.x = ALPHA_N * (acc[s][0] + br0) + nz0.x;
        d0.y = ALPHA_N * (acc[s][1] + br1) + nz0.y;
        d1.x = ALPHA_N * (acc[s][2] + br0) + nz1.x;
        d1.y = ALPHA_N * (acc[s][3] + br1) + nz1.y;
        *reinterpret_cast<float2*>(&g_drive[(size_t)r0 * NH + gc]) = d0;
        *reinterpret_cast<float2*>(&g_drive[(size_t)r1 * NH + gc]) = d1;
    }
}

// ---------------- persistent step kernel -----------------------------------
// 128 CTAs = 16 b-groups (16 rows each) x 8 h-slices (64 cols each).
// State in registers; w_rnn slice resident in smem; rpost exchanged via L2
// with per-group 8-CTA barriers (one per step).
#define SMEM_STEP (256 * 68 * 4 + 16 * 520 * 2)   // 69632 + 16640 = 86272 B

__global__ void __launch_bounds__(256) step_kernel(
    const float* __restrict__ x_init, const float* __restrict__ sx_init,
    const float* __restrict__ su_init,
    const float* __restrict__ a_std, const float* __restrict__ a_stf,
    const float* __restrict__ Uv, const float* __restrict__ dynv,
    float* __restrict__ out_x)
{
    extern __shared__ uint8_t smem[];
    uint32_t* wp = reinterpret_cast<uint32_t*>(smem);                 // [256 pairs][68]
    __half*   rp = reinterpret_cast<__half*>(smem + 256 * 68 * 4);    // [16][520]

    int cta   = blockIdx.x;
    int grp   = cta >> 3;     // 0..15 (batch group)
    int slice = cta & 7;      // 0..7  (h slice)
    int b0 = grp * 16;
    int h0 = slice * 64;
    int tid = threadIdx.x;
    int w = tid >> 5, lane = tid & 31;
    int g = lane >> 2, t = lane & 3;

    // load persistent w_rnn slice (cols h0..h0+63) into smem, packed k-pairs
    #pragma unroll
    for (int j = 0; j < 64; j++) {
        int idx = tid + j * 256;
        int p = idx >> 6, c = idx & 63;
        wp[p * 68 + c] = g_wrnnp[p * NH + h0 + c];
    }

    // element ownership == mma accumulator layout:
    // e0=(b0+g, hb), e1=(b0+g, hb+1), e2=(b0+g+8, hb), e3=(b0+g+8, hb+1)
    int hb  = h0 + 8 * w + 2 * t;
    int br0 = b0 + g, br1 = b0 + g + 8;

    float as0 = a_std[hb], as1 = a_std[hb + 1];
    float af0 = a_stf[hb], af1 = a_stf[hb + 1];
    float U0  = Uv[hb],    U1  = Uv[hb + 1];
    float dy0 = dynv[hb],  dy1 = dynv[hb + 1];

    float x0 = x_init[br0 * NH + hb],     x1 = x_init[br0 * NH + hb + 1];
    float x2 = x_init[br1 * NH + hb],     x3 = x_init[br1 * NH + hb + 1];
    float sx0 = sx_init[br0 * NH + hb],   sx1 = sx_init[br0 * NH + hb + 1];
    float sx2 = sx_init[br1 * NH + hb],   sx3 = sx_init[br1 * NH + hb + 1];
    float su0 = su_init[br0 * NH + hb],   su1 = su_init[br0 * NH + hb + 1];
    float su2 = su_init[br1 * NH + hb],   su3 = su_init[br1 * NH + hb + 1];

    __half2* rgl = reinterpret_cast<__half2*>(g_rpost);
    __syncthreads();

    for (int ts = 0; ts < T_STEPS; ts++) {
        // ---- phase 1: STP update + x_post + rpost (own elements only) ----
        float xp0, xp1, xp2, xp3;
        {
            float r, sxn, sun;
            r = fmaxf(x0, 0.f);
            sxn = sx0 + (as0 * (1.f - sx0) - DTSEC * su0 * sx0 * r) * dy0;
            sun = su0 + (af0 * (U0 - su0) + DTSEC * U0 * (1.f - su0) * r) * dy0;
            sx0 = fminf(fmaxf(sxn, 0.f), 1.f); su0 = fminf(fmaxf(sun, 0.f), 1.f);
            xp0 = su0 * sx0 * x0;

            r = fmaxf(x1, 0.f);
            sxn = sx1 + (as1 * (1.f - sx1) - DTSEC * su1 * sx1 * r) * dy1;
            sun = su1 + (af1 * (U1 - su1) + DTSEC * U1 * (1.f - su1) * r) * dy1;
            sx1 = fminf(fmaxf(sxn, 0.f), 1.f); su1 = fminf(fmaxf(sun, 0.f), 1.f);
            xp1 = su1 * sx1 * x1;

            r = fmaxf(x2, 0.f);
            sxn = sx2 + (as0 * (1.f - sx2) - DTSEC * su2 * sx2 * r) * dy0;
            sun = su2 + (af0 * (U0 - su2) + DTSEC * U0 * (1.f - su2) * r) * dy0;
            sx2 = fminf(fmaxf(sxn, 0.f), 1.f); su2 = fminf(fmaxf(sun, 0.f), 1.f);
            xp2 = su2 * sx2 * x2;

            r = fmaxf(x3, 0.f);
            sxn = sx3 + (as1 * (1.f - sx3) - DTSEC * su3 * sx3 * r) * dy1;
            sun = su3 + (af1 * (U1 - su3) + DTSEC * U1 * (1.f - su3) * r) * dy1;
            sx3 = fminf(fmaxf(sxn, 0.f), 1.f); su3 = fminf(fmaxf(sun, 0.f), 1.f);
            xp3 = su3 * sx3 * x3;
        }
        int buf = ts & 1;
        rgl[(buf * BATCH * NH + br0 * NH + hb) >> 1] =
            __floats2half2_rn(fmaxf(xp0, 0.f), fmaxf(xp1, 0.f));
        rgl[(buf * BATCH * NH + br1 * NH + hb) >> 1] =
            __floats2half2_rn(fmaxf(xp2, 0.f), fmaxf(xp3, 0.f));

        // ---- group barrier (8 CTAs sharing the same 16 batch rows) ----
        __threadfence();
        __syncthreads();
        if (tid == 0) {
            unsigned* c = &g_bar[grp * T_STEPS + ts];
            atomicAdd(c, 1u);
            while (*((volatile unsigned*)c) < 8u) { }
            __threadfence();
        }
        __syncthreads();

        // ---- stage rpost rows [16][512] fp16 from L2 into smem ----
        const uint4* src = reinterpret_cast<const uint4*>(g_rpost + buf * BATCH * NH);
        uint4* dst = reinterpret_cast<uint4*>(rp);
        #pragma unroll
        for (int j = 0; j < 4; j++) {
            int idx = tid + j * 256;
            int row = idx >> 6, c8 = idx & 63;
            dst[row * 65 + c8] = src[(b0 + row) * 64 + c8];   // 520-half rows = 65 uint4
        }
        __syncthreads();

        // ---- mma: C[16x64] += rpost[16x512] @ W[512x64] ----
        float acc0 = 0.f, acc1 = 0.f, acc2 = 0.f, acc3 = 0.f;
        #pragma unroll
        for (int kk = 0; kk < 32; kk++) {
            int k0 = kk * 16;
            uint32_t a0 = *reinterpret_cast<const uint32_t*>(rp + g * 520 + k0 + 2 * t);
            uint32_t a1 = *reinterpret_cast<const uint32_t*>(rp + (g + 8) * 520 + k0 + 2 * t);
            uint32_t a2 = *reinterpret_cast<const uint32_t*>(rp + g * 520 + k0 + 8 + 2 * t);
            uint32_t a3 = *reinterpret_cast<const uint32_t*>(rp + (g + 8) * 520 + k0 + 8 + 2 * t);
            uint32_t b0r = wp[(kk * 8 + t) * 68 + 8 * w + g];
            uint32_t b1r = wp[(kk * 8 + t + 4) * 68 + 8 * w + g];
            asm volatile("mma.sync.aligned.m16n8k16.row.col.f32.f16.f16.f32 "
                         "{%0,%1,%2,%3}, {%4,%5,%6,%7}, {%8,%9}, {%0,%1,%2,%3};"
                         : "+f"(acc0), "+f"(acc1), "+f"(acc2), "+f"(acc3)
                         : "r"(a0), "r"(a1), "r"(a2), "r"(a3), "r"(b0r), "r"(b1r));
        }
        __syncthreads();   // protect rp before next step's reuse (cheap, in-CTA)

        // ---- epilogue: x_new = 0.8*x_post + 0.2*acc + drive; store x_seq ----
        float2 d0 = *reinterpret_cast<const float2*>(&g_drive[((size_t)ts * BATCH + br0) * NH + hb]);
        float2 d1 = *reinterpret_cast<const float2*>(&g_drive[((size_t)ts * BATCH + br1) * NH + hb]);
        x0 = (1.f - ALPHA_N) * xp0 + ALPHA_N * acc0 + d0.x;
        x1 = (1.f - ALPHA_N) * xp1 + ALPHA_N * acc1 + d0.y;
        x2 = (1.f - ALPHA_N) * xp2 + ALPHA_N * acc2 + d1.x;
        x3 = (1.f - ALPHA_N) * xp3 + ALPHA_N * acc3 + d1.y;
        *reinterpret_cast<float2*>(&out_x[((size_t)br0 * T_STEPS + ts) * NH + hb]) = make_float2(x0, x1);
        *reinterpret_cast<float2*>(&out_x[((size_t)br1 * T_STEPS + ts) * NH + hb]) = make_float2(x2, x3);
    }
}

// ---------------- y = relu(x) @ w_out_eff + b_out (one warp per (t,b)) -----
__global__ void __launch_bounds__(256) y_kernel(const float* __restrict__ out_x,
                                                const float* __restrict__ b_out)
{
    __shared__ float wsh[NH * NOUT];
    for (int i = threadIdx.x; i < NH * NOUT; i += 256) wsh[i] = g_wout[i];
    __syncthreads();

    int w = threadIdx.x >> 5, lane = threadIdx.x & 31;
    int row = blockIdx.x * 8 + w;           // 0..76799 = t*256 + b
    int t = row >> 8;
    int b = row & 255;
    const float* xr = out_x + ((size_t)b * T_STEPS + t) * NH;

    float a0 = 0.f, a1 = 0.f, a2 = 0.f;
    #pragma unroll 4
    for (int h = lane; h < NH; h += 32) {
        float r = fmaxf(xr[h], 0.f);
        a0 += r * wsh[h * 3 + 0];
        a1 += r * wsh[h * 3 + 1];
        a2 += r * wsh[h * 3 + 2];
    }
    #pragma unroll
    for (int off = 16; off > 0; off >>= 1) {
        a0 += __shfl_xor_sync(0xffffffffu, a0, off);
        a1 += __shfl_xor_sync(0xffffffffu, a1, off);
        a2 += __shfl_xor_sync(0xffffffffu, a2, off);
    }
    if (lane == 0) {
        size_t base = ((size_t)t * BATCH + b) * NOUT;
        g_yraw[base + 0] = a0 + b_out[0];
        g_yraw[base + 1] = a1 + b_out[1];
        g_yraw[base + 2] = a2 + b_out[2];
    }
}

// ---------------- softmax over batch axis, write [B,T,NOUT] ----------------
__global__ void __launch_bounds__(256) softmax_kernel(float* __restrict__ out_y)
{
    __shared__ float red[256];
    int t = blockIdx.x;
    int b = threadIdx.x;
    float v[NOUT], e[NOUT];
    #pragma unroll
    for (int o = 0; o < NOUT; o++)
        v[o] = g_yraw[((size_t)t * BATCH + b) * NOUT + o];

    #pragma unroll
    for (int o = 0; o < NOUT; o++) {
        red[b] = v[o];
        __syncthreads();
        for (int s = 128; s > 0; s >>= 1) {
            if (b < s) red[b] = fmaxf(red[b], red[b + s]);
            __syncthreads();
        }
        float mx = red[0];
        __syncthreads();
        e[o] = expf(v[o] - mx);
        red[b] = e[o];
        __syncthreads();
        for (int s = 128; s > 0; s >>= 1) {
            if (b < s) red[b] += red[b + s];
            __syncthreads();
        }
        float sm = red[0];
        __syncthreads();
        out_y[((size_t)b * T_STEPS + t) * NOUT + o] = e[o] / sm;
    }
}

// ---------------- launch ----------------------------------------------------
extern "C" void kernel_launch(void* const* d_in, const int* in_sizes, int n_in,
                              void* d_out, int out_size)
{
    const float* input_data = (const float*)d_in[0];
    const float* noise      = (const float*)d_in[1];
    const float* x_init     = (const float*)d_in[2];
    const float* syn_x_init = (const float*)d_in[3];
    const float* syn_u_init = (const float*)d_in[4];
    const float* w_in       = (const float*)d_in[5];
    const float* w_in_mask  = (const float*)d_in[6];
    const float* w_rnn_base = (const float*)d_in[7];
    const float* conn_mask  = (const float*)d_in[8];
    const float* ei_matrix  = (const float*)d_in[9];
    const float* b_rnn      = (const float*)d_in[10];
    const float* w_out      = (const float*)d_in[11];
    const float* w_out_mask = (const float*)d_in[12];
    const float* b_out      = (const float*)d_in[13];
    const float* a_std      = (const float*)d_in[14];
    const float* a_stf      = (const float*)d_in[15];
    const float* Uv         = (const float*)d_in[16];
    const float* dynv       = (const float*)d_in[17];

    float* out   = (float*)d_out;
    float* out_y = out;
    float* out_x = out + Y_SIZE;

    cudaFuncSetAttribute(step_kernel, cudaFuncAttributeMaxDynamicSharedMemorySize, SMEM_STEP);

    prep_kernel<<<64, 256>>>(w_in, w_in_mask, w_rnn_base, conn_mask, ei_matrix,
                             w_out, w_out_mask);
    dim3 dgrid(76800 / 64, NH / 64);
    drive_gemm<<<dgrid, 256>>>(input_data, noise, b_rnn);
    step_kernel<<<128, 256, SMEM_STEP>>>(x_init, syn_x_init, syn_u_init,
                                         a_std, a_stf, Uv, dynv, out_x);
    y_kernel<<<76800 / 8, 256>>>(out_x, b_out);
    softmax_kernel<<<T_STEPS, 256>>>(out_y);
}